// round 4
// baseline (speedup 1.0000x reference)
#include <cuda_runtime.h>
#include <cuda_fp16.h>

#define TPB 256
#define MAX_LAYERS 64
typedef unsigned long long ull;

// ---------- packed f32x2 primitives (sm_100+; rt~2 per instr for 2 floats) ----------
__device__ __forceinline__ ull f2fma(ull a, ull b, ull c) {
    ull d; asm("fma.rn.f32x2 %0, %1, %2, %3;" : "=l"(d) : "l"(a), "l"(b), "l"(c)); return d;
}
__device__ __forceinline__ ull f2mul(ull a, ull b) {
    ull d; asm("mul.rn.f32x2 %0, %1, %2;" : "=l"(d) : "l"(a), "l"(b)); return d;
}
__device__ __forceinline__ ull f2add(ull a, ull b) {
    ull d; asm("add.rn.f32x2 %0, %1, %2;" : "=l"(d) : "l"(a), "l"(b)); return d;
}
__device__ __forceinline__ ull pk2(float x) {           // duplicate float into both halves
    ull r; asm("mov.b64 %0, {%1, %1};" : "=l"(r) : "f"(x)); return r;
}
__device__ __forceinline__ ull pkf(float lo, float hi) {
    ull r; asm("mov.b64 %0, {%1, %2};" : "=l"(r) : "f"(lo), "f"(hi)); return r;
}
__device__ __forceinline__ void unpku(ull v, unsigned& lo, unsigned& hi) {
    asm("mov.b64 {%0, %1}, %2;" : "=r"(lo), "=r"(hi) : "l"(v));
}
__device__ __forceinline__ ull pku(unsigned lo, unsigned hi) {
    ull r; asm("mov.b64 %0, {%1, %2};" : "=l"(r) : "r"(lo), "r"(hi)); return r;
}

// MUFU-free tanh of both packed f32 halves: fma pipe + alu (LOP3/IMAD) only.
// tanh(x) = sign(x) * (1-u)/(1+u),  u = exp(-2|x|) = 2^(-2|x|*log2e)
__device__ __forceinline__ ull tanh2_fma(ull y) {
    const ull ABS = 0x7FFFFFFF7FFFFFFFull;
    const ull SGN = 0x8000000080000000ull;
    ull a = y & ABS;                         // |x| per half     (alu)
    ull s = y & SGN;                         // sign bits        (alu)
    ull w  = f2mul(a, pk2(-2.885390081777927f));     // w = -2|x|*log2e  <= 0
    ull kf = f2add(w, pk2(12582912.0f));             // round-to-nearest via magic
    ull kb = f2add(kf, pk2(-12582912.0f));           // k as float
    ull f  = f2fma(kb, pk2(-1.0f), w);               // f = w - k, |f| <= 0.5
    // 2^f, deg-4 Taylor in ln2 (|f|<=0.5 -> rel err ~4e-5)
    ull p = f2fma(f, pk2(0.009618129107f), pk2(0.055504108664f));
    p = f2fma(f, p, pk2(0.240226506959f));
    p = f2fma(f, p, pk2(0.693147180560f));
    p = f2fma(f, p, pk2(1.0f));
    // u = p * 2^k : add k (low bits of kf) into exponent field, per half (IMAD on fma pipe)
    unsigned plo, phi, klo, khi;
    unpku(p, plo, phi);
    unpku(kf, klo, khi);
    unsigned ulo = plo + (klo << 23);
    unsigned uhi = phi + (khi << 23);
    ull u = pku(ulo, uhi);                           // u = e^{-2|x|} in (0,1]
    // r = 1/(1+u): quadratic seed + 2 Newton (division-free)
    ull d  = f2add(u, pk2(1.0f));                    // d in [1,2]
    ull r  = f2fma(d, f2fma(d, pk2(0.3333333f), pk2(-1.5f)), pk2(2.1666667f));
    ull e  = f2fma(d, r, pk2(-1.0f));
    r = f2fma(e ^ SGN, r, r);                        // r -= r*e
    e = f2fma(d, r, pk2(-1.0f));
    r = f2fma(e ^ SGN, r, r);
    ull g = f2add(u, pk2(-1.0f));                    // u-1  (<= 0)
    ull h = f2mul(g, r);                             // -(tanh|x|)  (<= 0)
    return (h & ABS) | s;                            // |h| with sign of x (1 LOP3/half)
}

__device__ __forceinline__ __half2 tanh_h2(__half2 x) {
    __half2 y;
    asm("tanh.approx.f16x2 %0, %1;"
        : "=r"(*reinterpret_cast<unsigned int*>(&y))
        : "r"(*reinterpret_cast<const unsigned int*>(&x)));
    return y;
}

// 2 points per thread. Block-specialized: 13/16 blocks run the MUFU half2 path (A),
// 3/16 run the MUFU-free f32x2 path (B). Pipes (MUFU vs FMA) balance chip-wide.
// z-form: z = 2x for l>=1 (0.5 folded into W); final normalize is scale-invariant.
__global__ __launch_bounds__(TPB, 6) void nignet_kernel(
    const float4* __restrict__ pts,
    const float*  __restrict__ Ws,    // (L,2,2)
    const float*  __restrict__ bs,    // (L,2)
    const float*  __restrict__ fW,    // (2,2)
    float4* __restrict__ out,
    int nf4,
    int layers)
{
    __shared__ __align__(16) __half2 sw[MAX_LAYERS][4];
    __shared__ __align__(8)  __half2 sb[MAX_LAYERS][2];
    __shared__ __align__(16) ull     swB[MAX_LAYERS][6];   // f32x2-duplicated w00..w11,b0,b1
    __shared__ float sf[4];

    const int tid = threadIdx.x;
    if (tid < layers) {
        const float scl = (tid == 0) ? 1.0f : 0.5f;
        float4 w = ((const float4*)Ws)[tid];
        float2 b = ((const float2*)bs)[tid];
        float w00 = w.x * scl, w01 = w.y * scl, w10 = w.z * scl, w11 = w.w * scl;
        sw[tid][0] = __float2half2_rn(w00);
        sw[tid][1] = __float2half2_rn(w01);
        sw[tid][2] = __float2half2_rn(w10);
        sw[tid][3] = __float2half2_rn(w11);
        sb[tid][0] = __float2half2_rn(b.x);
        sb[tid][1] = __float2half2_rn(b.y);
        swB[tid][0] = pkf(w00, w00);
        swB[tid][1] = pkf(w01, w01);
        swB[tid][2] = pkf(w10, w10);
        swB[tid][3] = pkf(w11, w11);
        swB[tid][4] = pkf(b.x, b.x);
        swB[tid][5] = pkf(b.y, b.y);
    }
    if (tid < 4) sf[tid] = fW[tid];
    __syncthreads();

    const int idx = blockIdx.x * TPB + tid;
    if (idx >= nf4) return;

    float4 v = pts[idx];                 // point A=(v.x,v.y), B=(v.z,v.w)
    float a0x, a0y, a1x, a1y;            // final states (fp32), A=(x) B=(y)

    const bool isB = ((blockIdx.x & 15) < 3);

    if (!isB) {
        // ---- A path: MUFU tanh, fp16x2 state (proven R3 path) ----
        __half2 X0 = __floats2half2_rn(v.x, v.z);
        __half2 X1 = __floats2half2_rn(v.y, v.w);
        #pragma unroll 4
        for (int l = 0; l < layers; ++l) {
            const __half2 w00 = sw[l][0], w01 = sw[l][1];
            const __half2 w10 = sw[l][2], w11 = sw[l][3];
            const __half2 b0  = sb[l][0], b1  = sb[l][1];
            __half2 y0 = __hfma2(w00, X0, __hfma2(w01, X1, b0));
            __half2 y1 = __hfma2(w10, X0, __hfma2(w11, X1, b1));
            __half2 t0 = tanh_h2(y0);
            __half2 t1 = tanh_h2(y1);
            X0 = __hadd2(t0, y0);
            X1 = __hadd2(t1, y1);
        }
        float2 f0 = __half22float2(X0);
        float2 f1 = __half22float2(X1);
        a0x = f0.x; a0y = f0.y; a1x = f1.x; a1y = f1.y;
    } else {
        // ---- B path: MUFU-free tanh, packed f32x2 state ----
        ull X0 = pkf(v.x, v.z);
        ull X1 = pkf(v.y, v.w);
        #pragma unroll 2
        for (int l = 0; l < layers; ++l) {
            const ull w00 = swB[l][0], w01 = swB[l][1];
            const ull w10 = swB[l][2], w11 = swB[l][3];
            const ull b0  = swB[l][4], b1  = swB[l][5];
            ull y0 = f2fma(w00, X0, f2fma(w01, X1, b0));
            ull y1 = f2fma(w10, X0, f2fma(w11, X1, b1));
            X0 = f2add(tanh2_fma(y0), y0);
            X1 = f2add(tanh2_fma(y1), y1);
        }
        unsigned u0, u1, u2, u3;
        unpku(X0, u0, u1);
        unpku(X1, u2, u3);
        a0x = __uint_as_float(u0); a0y = __uint_as_float(u1);
        a1x = __uint_as_float(u2); a1y = __uint_as_float(u3);
    }

    // Epilogue (fp32): final matvec + L2 row-normalize.
    const float f00 = sf[0], f01 = sf[1], f10 = sf[2], f11 = sf[3];
    float4 r;
    {
        float o0 = fmaf(f00, a0x, f01 * a1x);
        float o1 = fmaf(f10, a0x, f11 * a1x);
        float s  = fmaf(o0, o0, o1 * o1);
        float inv = rsqrtf(s);
        inv = inv * fmaf(-0.5f * s * inv, inv, 1.5f);
        if (s < 1e-24f) inv = 1e12f;
        r.x = o0 * inv;
        r.y = o1 * inv;
    }
    {
        float o0 = fmaf(f00, a0y, f01 * a1y);
        float o1 = fmaf(f10, a0y, f11 * a1y);
        float s  = fmaf(o0, o0, o1 * o1);
        float inv = rsqrtf(s);
        inv = inv * fmaf(-0.5f * s * inv, inv, 1.5f);
        if (s < 1e-24f) inv = 1e12f;
        r.z = o0 * inv;
        r.w = o1 * inv;
    }
    out[idx] = r;
}

extern "C" void kernel_launch(void* const* d_in, const int* in_sizes, int n_in,
                              void* d_out, int out_size) {
    // metadata order: T(1), closed_manifold(N*2), Ws(L*4), bs(L*2), final_W(4)
    const float* pts = (const float*)d_in[1];
    const float* Ws  = (const float*)d_in[2];
    const float* bs  = (const float*)d_in[3];
    const float* fW  = (const float*)d_in[4];
    float* out = (float*)d_out;

    const int n      = in_sizes[1] / 2;
    const int layers = in_sizes[2] / 4;
    const int nf4    = n / 2;

    const int grid = (nf4 + TPB - 1) / TPB;
    nignet_kernel<<<grid, TPB>>>(
        (const float4*)pts, Ws, bs, fW, (float4*)out, nf4, layers);
}

// round 5
// speedup vs baseline: 1.1149x; 1.1149x over previous
#include <cuda_runtime.h>
#include <cuda_fp16.h>

#define TPB 512
#define MAX_LAYERS 64
typedef unsigned long long ull;

// ---------- packed f32x2 primitives (sm_103a FFMA2 path) ----------
__device__ __forceinline__ ull f2fma(ull a, ull b, ull c) {
    ull d; asm("fma.rn.f32x2 %0, %1, %2, %3;" : "=l"(d) : "l"(a), "l"(b), "l"(c)); return d;
}
__device__ __forceinline__ ull f2mul(ull a, ull b) {
    ull d; asm("mul.rn.f32x2 %0, %1, %2;" : "=l"(d) : "l"(a), "l"(b)); return d;
}
__device__ __forceinline__ ull f2add(ull a, ull b) {
    ull d; asm("add.rn.f32x2 %0, %1, %2;" : "=l"(d) : "l"(a), "l"(b)); return d;
}
__device__ __forceinline__ ull pkf(float lo, float hi) {
    ull r; asm("mov.b64 %0, {%1, %2};" : "=l"(r) : "f"(lo), "f"(hi)); return r;
}
__device__ __forceinline__ ull pk2(float x) { return pkf(x, x); }
__device__ __forceinline__ void unpku(ull v, unsigned& lo, unsigned& hi) {
    asm("mov.b64 {%0, %1}, %2;" : "=r"(lo), "=r"(hi) : "l"(v));
}
__device__ __forceinline__ ull pku(unsigned lo, unsigned hi) {
    ull r; asm("mov.b64 %0, {%1, %2};" : "=l"(r) : "r"(lo), "r"(hi)); return r;
}

// MUFU-free packed tanh: tanh(x) = sign(x)*(1-u)/(1+u), u = 2^(-2|x|*log2e).
// 15 f32x2 (fma pipe) + ~10 int ops (alu pipe). abs err <~ 3e-4.
__device__ __forceinline__ ull tanh2_fma(ull y) {
    const unsigned ABS32 = 0x7FFFFFFFu;
    const ull ABS = 0x7FFFFFFF7FFFFFFFull;
    ull a  = y & ABS;                                  // |x|       (2 LOP3, alu)
    ull w  = f2mul(a, pk2(-2.885390081777927f));       // -2|x|*log2e
    ull kf = f2add(w, pk2(12582912.0f));               // magic round
    ull kb = f2add(kf, pk2(-12582912.0f));             // k as float
    ull f  = f2fma(kb, pk2(-1.0f), w);                 // f = w - k, |f|<=0.5
    ull p  = f2fma(f, pk2(0.009618129107f), pk2(0.055504108664f));
    p = f2fma(f, p, pk2(0.240226506959f));
    p = f2fma(f, p, pk2(0.693147180560f));
    p = f2fma(f, p, pk2(1.0f));                        // 2^f
    unsigned klo, khi, plo, phi;
    unpku(kf, klo, khi);
    unpku(p,  plo, phi);
    // clamp k >= -126 (monotone in kf bits), then exponent insert (LEA)
    const int KMIN = 0x4B3FFF82;                       // bits(12582912-126)
    int kli = max((int)klo, KMIN);
    int khi2 = max((int)khi, KMIN);
    unsigned ulo = plo + ((unsigned)kli << 23);
    unsigned uhi = phi + ((unsigned)khi2 << 23);
    ull u = pku(ulo, uhi);                             // e^{-2|x|} in (0,1]
    ull d  = f2add(u, pk2(1.0f));                      // d in (1,2]
    ull nd = d ^ 0x8000000080000000ull;                // -d      (2 LOP3, alu)
    ull r  = f2fma(d, f2fma(d, pk2(0.33333333f), pk2(-1.5f)), pk2(2.16666667f));
    ull t  = f2fma(nd, r, pk2(2.0f));                  // Newton: r*(2-d*r)
    r = f2mul(r, t);
    ull g = f2add(u, pk2(-1.0f));                      // u-1 (<=0)
    ull h = f2mul(g, r);                               // -tanh|x|
    // sign transfer: (|h|) with sign of y — one LOP3 per half
    unsigned hlo, hhi, ylo, yhi;
    unpku(h, hlo, hhi);
    unpku(y, ylo, yhi);
    unsigned rlo = (hlo & ABS32) | (ylo & 0x80000000u);
    unsigned rhi = (hhi & ABS32) | (yhi & 0x80000000u);
    return pku(rlo, rhi);
}

__device__ __forceinline__ __half2 tanh_h2(__half2 x) {
    __half2 y;
    asm("tanh.approx.f16x2 %0, %1;"
        : "=r"(*reinterpret_cast<unsigned int*>(&y))
        : "r"(*reinterpret_cast<const unsigned int*>(&x)));
    return y;
}

// 2 points/thread. Warp-specialized: wid 0-3 -> fma-pipe tanh (B), wid 4-15 ->
// MUFU half2 tanh (A). SMSP = wid%4, so every SMSP holds exactly 3A+1B:
// MUFU 96 cyc vs fma 108 cyc per block-SMSP-layer (vs 128 pure MUFU).
// z-form: z = 2x for l>=1 (0.5 folded into W); final normalize is scale-invariant.
__global__ __launch_bounds__(TPB, 3) void nignet_kernel(
    const float4* __restrict__ pts,
    const float*  __restrict__ Ws,    // (L,2,2)
    const float*  __restrict__ bs,    // (L,2)
    const float*  __restrict__ fW,    // (2,2)
    float4* __restrict__ out,
    int nf4,
    int layers)
{
    __shared__ __align__(16) __half2 sw[MAX_LAYERS][4];
    __shared__ __align__(8)  __half2 sb[MAX_LAYERS][2];
    __shared__ __align__(16) ull     swB[MAX_LAYERS][6];
    __shared__ float sf[4];

    const int tid = threadIdx.x;
    if (tid < layers) {
        const float scl = (tid == 0) ? 1.0f : 0.5f;
        float4 w = ((const float4*)Ws)[tid];
        float2 b = ((const float2*)bs)[tid];
        float w00 = w.x * scl, w01 = w.y * scl, w10 = w.z * scl, w11 = w.w * scl;
        sw[tid][0] = __float2half2_rn(w00);
        sw[tid][1] = __float2half2_rn(w01);
        sw[tid][2] = __float2half2_rn(w10);
        sw[tid][3] = __float2half2_rn(w11);
        sb[tid][0] = __float2half2_rn(b.x);
        sb[tid][1] = __float2half2_rn(b.y);
        swB[tid][0] = pk2(w00);
        swB[tid][1] = pk2(w01);
        swB[tid][2] = pk2(w10);
        swB[tid][3] = pk2(w11);
        swB[tid][4] = pk2(b.x);
        swB[tid][5] = pk2(b.y);
    }
    if (tid < 4) sf[tid] = fW[tid];
    __syncthreads();

    const int idx = blockIdx.x * TPB + tid;
    if (idx >= nf4) return;

    float4 v = pts[idx];
    float a0x, a0y, a1x, a1y;

    const int wid = tid >> 5;

    if (wid >= 4) {
        // ---- A: MUFU tanh, fp16x2 state ----
        __half2 X0 = __floats2half2_rn(v.x, v.z);
        __half2 X1 = __floats2half2_rn(v.y, v.w);
        #pragma unroll 4
        for (int l = 0; l < layers; ++l) {
            const __half2 w00 = sw[l][0], w01 = sw[l][1];
            const __half2 w10 = sw[l][2], w11 = sw[l][3];
            const __half2 b0  = sb[l][0], b1  = sb[l][1];
            __half2 y0 = __hfma2(w00, X0, __hfma2(w01, X1, b0));
            __half2 y1 = __hfma2(w10, X0, __hfma2(w11, X1, b1));
            __half2 t0 = tanh_h2(y0);
            __half2 t1 = tanh_h2(y1);
            X0 = __hadd2(t0, y0);
            X1 = __hadd2(t1, y1);
        }
        float2 f0 = __half22float2(X0);
        float2 f1 = __half22float2(X1);
        a0x = f0.x; a0y = f0.y; a1x = f1.x; a1y = f1.y;
    } else {
        // ---- B: fma-pipe tanh, packed f32x2 state ----
        ull X0 = pkf(v.x, v.z);
        ull X1 = pkf(v.y, v.w);
        #pragma unroll 2
        for (int l = 0; l < layers; ++l) {
            const ull w00 = swB[l][0], w01 = swB[l][1];
            const ull w10 = swB[l][2], w11 = swB[l][3];
            const ull b0  = swB[l][4], b1  = swB[l][5];
            ull y0 = f2fma(w00, X0, f2fma(w01, X1, b0));
            ull y1 = f2fma(w10, X0, f2fma(w11, X1, b1));
            X0 = f2add(tanh2_fma(y0), y0);
            X1 = f2add(tanh2_fma(y1), y1);
        }
        unsigned u0, u1, u2, u3;
        unpku(X0, u0, u1);
        unpku(X1, u2, u3);
        a0x = __uint_as_float(u0); a0y = __uint_as_float(u1);
        a1x = __uint_as_float(u2); a1y = __uint_as_float(u3);
    }

    // Epilogue (fp32): final matvec + L2 row-normalize.
    const float f00 = sf[0], f01 = sf[1], f10 = sf[2], f11 = sf[3];
    float4 r;
    {
        float o0 = fmaf(f00, a0x, f01 * a1x);
        float o1 = fmaf(f10, a0x, f11 * a1x);
        float s  = fmaf(o0, o0, o1 * o1);
        float inv = rsqrtf(s);
        inv = inv * fmaf(-0.5f * s * inv, inv, 1.5f);
        if (s < 1e-24f) inv = 1e12f;
        r.x = o0 * inv;
        r.y = o1 * inv;
    }
    {
        float o0 = fmaf(f00, a0y, f01 * a1y);
        float o1 = fmaf(f10, a0y, f11 * a1y);
        float s  = fmaf(o0, o0, o1 * o1);
        float inv = rsqrtf(s);
        inv = inv * fmaf(-0.5f * s * inv, inv, 1.5f);
        if (s < 1e-24f) inv = 1e12f;
        r.z = o0 * inv;
        r.w = o1 * inv;
    }
    out[idx] = r;
}

extern "C" void kernel_launch(void* const* d_in, const int* in_sizes, int n_in,
                              void* d_out, int out_size) {
    // metadata order: T(1), closed_manifold(N*2), Ws(L*4), bs(L*2), final_W(4)
    const float* pts = (const float*)d_in[1];
    const float* Ws  = (const float*)d_in[2];
    const float* bs  = (const float*)d_in[3];
    const float* fW  = (const float*)d_in[4];
    float* out = (float*)d_out;

    const int n      = in_sizes[1] / 2;
    const int layers = in_sizes[2] / 4;
    const int nf4    = n / 2;

    const int grid = (nf4 + TPB - 1) / TPB;
    nignet_kernel<<<grid, TPB>>>(
        (const float4*)pts, Ws, bs, fW, (float4*)out, nf4, layers);
}

// round 6
// speedup vs baseline: 1.1322x; 1.0156x over previous
#include <cuda_runtime.h>
#include <cuda_fp16.h>

#define TPB 512
#define MAX_LAYERS 64
typedef unsigned long long ull;

// ---------- packed f32x2 primitives (sm_103a FFMA2 path) ----------
__device__ __forceinline__ ull f2fma(ull a, ull b, ull c) {
    ull d; asm("fma.rn.f32x2 %0, %1, %2, %3;" : "=l"(d) : "l"(a), "l"(b), "l"(c)); return d;
}
__device__ __forceinline__ ull f2mul(ull a, ull b) {
    ull d; asm("mul.rn.f32x2 %0, %1, %2;" : "=l"(d) : "l"(a), "l"(b)); return d;
}
__device__ __forceinline__ ull f2add(ull a, ull b) {
    ull d; asm("add.rn.f32x2 %0, %1, %2;" : "=l"(d) : "l"(a), "l"(b)); return d;
}
__device__ __forceinline__ ull pkf(float lo, float hi) {
    ull r; asm("mov.b64 %0, {%1, %2};" : "=l"(r) : "f"(lo), "f"(hi)); return r;
}
__device__ __forceinline__ ull pk2(float x) { return pkf(x, x); }
__device__ __forceinline__ void unpku(ull v, unsigned& lo, unsigned& hi) {
    asm("mov.b64 {%0, %1}, %2;" : "=r"(lo), "=r"(hi) : "l"(v));
}
__device__ __forceinline__ ull pku(unsigned lo, unsigned hi) {
    ull r; asm("mov.b64 %0, {%1, %2};" : "=l"(r) : "r"(lo), "r"(hi)); return r;
}

// MUFU-free packed tanh: tanh(x) = sign(x)*(1-u)/(1+u), u = 2^(-2|x|*log2e).
// 14 f32x2 (fma pipe) + ~8 int ops (alu pipe). tanh abs err ~1e-4.
__device__ __forceinline__ ull tanh2_fma(ull y) {
    const unsigned ABS32 = 0x7FFFFFFFu;
    const ull ABS = 0x7FFFFFFF7FFFFFFFull;
    ull a  = y & ABS;                                  // |x|        (alu)
    ull w  = f2mul(a, pk2(-2.885390081777927f));       // -2|x|*log2e (<= 0)
    ull kf = f2add(w, pk2(12582912.0f));               // magic round: bits hold k
    ull kb = f2add(kf, pk2(-12582912.0f));             // k as float (exact)
    ull f  = f2fma(kb, pk2(-1.0f), w);                 // f = w - k, |f| <= 0.5
    // 2^f, deg-3 minimax (c2 absorbs the t^4 term): rel err ~1.2e-4
    ull p = f2fma(f, pk2(0.0555042f), pk2(0.2422254f));
    p = f2fma(f, p, pk2(0.6931472f));
    p = f2fma(f, p, pk2(1.0f));
    unsigned klo, khi, plo, phi;
    unpku(kf, klo, khi);
    unpku(p,  plo, phi);
    // clamp k >= -126 (monotone in kf bits), then exponent insert
    const int KMIN = 0x4B3FFF82;                       // bits(12582912-126)
    int kli  = max((int)klo, KMIN);
    int khi2 = max((int)khi, KMIN);
    unsigned ulo = plo + ((unsigned)kli  << 23);
    unsigned uhi = phi + ((unsigned)khi2 << 23);
    ull u = pku(ulo, uhi);                             // e^{-2|x|} in (0,1]
    ull d  = f2add(u, pk2(1.0f));                      // d in (1,2]
    ull nd = d ^ 0x8000000080000000ull;                // -d (alu)
    ull r  = f2fma(d, f2fma(d, pk2(0.33333333f), pk2(-1.5f)), pk2(2.16666667f));
    ull t  = f2fma(nd, r, pk2(2.0f));                  // Newton: r*(2-d*r)
    r = f2mul(r, t);
    ull g = f2add(u, pk2(-1.0f));                      // u-1 (<= 0)
    ull h = f2mul(g, r);                               // -tanh|x|
    // sign transfer: |h| with sign of y — one LOP3 per half (alu)
    unsigned hlo, hhi, ylo, yhi;
    unpku(h, hlo, hhi);
    unpku(y, ylo, yhi);
    unsigned rlo = (hlo & ABS32) | (ylo & 0x80000000u);
    unsigned rhi = (hhi & ABS32) | (yhi & 0x80000000u);
    return pku(rlo, rhi);
}

__device__ __forceinline__ __half2 tanh_h2(__half2 x) {
    __half2 y;
    asm("tanh.approx.f16x2 %0, %1;"
        : "=r"(*reinterpret_cast<unsigned int*>(&y))
        : "r"(*reinterpret_cast<const unsigned int*>(&x)));
    return y;
}

// 2 points/thread. Warp-specialized: wid 0-3 -> fma-pipe tanh (B), wid 4-15 ->
// MUFU half2 tanh (A). SMSP = wid%4, so every SMSP holds exactly 3A+1B per block:
// per SMSP-layer fma ~104 cyc vs MUFU 96 (vs 128 for pure MUFU) -> co-terminating
// warps + ~1.23x pipe-level speedup.
// z-form: z = 2x for l>=1 (0.5 folded into W); final normalize is scale-invariant.
__global__ __launch_bounds__(TPB, 4) void nignet_kernel(
    const float4* __restrict__ pts,
    const float*  __restrict__ Ws,    // (L,2,2)
    const float*  __restrict__ bs,    // (L,2)
    const float*  __restrict__ fW,    // (2,2)
    float4* __restrict__ out,
    int nf4,
    int layers)
{
    __shared__ __align__(16) __half2 sw[MAX_LAYERS][4];
    __shared__ __align__(8)  __half2 sb[MAX_LAYERS][2];
    __shared__ __align__(16) ull     swB[MAX_LAYERS][6];
    __shared__ float sf[4];

    const int tid = threadIdx.x;
    if (tid < layers) {
        const float scl = (tid == 0) ? 1.0f : 0.5f;
        float4 w = ((const float4*)Ws)[tid];
        float2 b = ((const float2*)bs)[tid];
        float w00 = w.x * scl, w01 = w.y * scl, w10 = w.z * scl, w11 = w.w * scl;
        sw[tid][0] = __float2half2_rn(w00);
        sw[tid][1] = __float2half2_rn(w01);
        sw[tid][2] = __float2half2_rn(w10);
        sw[tid][3] = __float2half2_rn(w11);
        sb[tid][0] = __float2half2_rn(b.x);
        sb[tid][1] = __float2half2_rn(b.y);
        swB[tid][0] = pk2(w00);
        swB[tid][1] = pk2(w01);
        swB[tid][2] = pk2(w10);
        swB[tid][3] = pk2(w11);
        swB[tid][4] = pk2(b.x);
        swB[tid][5] = pk2(b.y);
    }
    if (tid < 4) sf[tid] = fW[tid];
    __syncthreads();

    const int idx = blockIdx.x * TPB + tid;
    if (idx >= nf4) return;

    float4 v = pts[idx];
    float a0x, a0y, a1x, a1y;

    const int wid = tid >> 5;

    if (wid >= 4) {
        // ---- A: MUFU tanh, fp16x2 state ----
        __half2 X0 = __floats2half2_rn(v.x, v.z);
        __half2 X1 = __floats2half2_rn(v.y, v.w);
        #pragma unroll 4
        for (int l = 0; l < layers; ++l) {
            const __half2 w00 = sw[l][0], w01 = sw[l][1];
            const __half2 w10 = sw[l][2], w11 = sw[l][3];
            const __half2 b0  = sb[l][0], b1  = sb[l][1];
            __half2 y0 = __hfma2(w00, X0, __hfma2(w01, X1, b0));
            __half2 y1 = __hfma2(w10, X0, __hfma2(w11, X1, b1));
            __half2 t0 = tanh_h2(y0);
            __half2 t1 = tanh_h2(y1);
            X0 = __hadd2(t0, y0);
            X1 = __hadd2(t1, y1);
        }
        float2 f0 = __half22float2(X0);
        float2 f1 = __half22float2(X1);
        a0x = f0.x; a0y = f0.y; a1x = f1.x; a1y = f1.y;
    } else {
        // ---- B: fma-pipe tanh, packed f32x2 state ----
        ull X0 = pkf(v.x, v.z);
        ull X1 = pkf(v.y, v.w);
        #pragma unroll 2
        for (int l = 0; l < layers; ++l) {
            const ull w00 = swB[l][0], w01 = swB[l][1];
            const ull w10 = swB[l][2], w11 = swB[l][3];
            const ull b0  = swB[l][4], b1  = swB[l][5];
            ull y0 = f2fma(w00, X0, f2fma(w01, X1, b0));
            ull y1 = f2fma(w10, X0, f2fma(w11, X1, b1));
            X0 = f2add(tanh2_fma(y0), y0);
            X1 = f2add(tanh2_fma(y1), y1);
        }
        unsigned u0, u1, u2, u3;
        unpku(X0, u0, u1);
        unpku(X1, u2, u3);
        a0x = __uint_as_float(u0); a0y = __uint_as_float(u1);
        a1x = __uint_as_float(u2); a1y = __uint_as_float(u3);
    }

    // Epilogue (fp32): final matvec + L2 row-normalize.
    const float f00 = sf[0], f01 = sf[1], f10 = sf[2], f11 = sf[3];
    float4 r;
    {
        float o0 = fmaf(f00, a0x, f01 * a1x);
        float o1 = fmaf(f10, a0x, f11 * a1x);
        float s  = fmaf(o0, o0, o1 * o1);
        float inv = rsqrtf(s);
        inv = inv * fmaf(-0.5f * s * inv, inv, 1.5f);
        if (s < 1e-24f) inv = 1e12f;
        r.x = o0 * inv;
        r.y = o1 * inv;
    }
    {
        float o0 = fmaf(f00, a0y, f01 * a1y);
        float o1 = fmaf(f10, a0y, f11 * a1y);
        float s  = fmaf(o0, o0, o1 * o1);
        float inv = rsqrtf(s);
        inv = inv * fmaf(-0.5f * s * inv, inv, 1.5f);
        if (s < 1e-24f) inv = 1e12f;
        r.z = o0 * inv;
        r.w = o1 * inv;
    }
    out[idx] = r;
}

extern "C" void kernel_launch(void* const* d_in, const int* in_sizes, int n_in,
                              void* d_out, int out_size) {
    // metadata order: T(1), closed_manifold(N*2), Ws(L*4), bs(L*2), final_W(4)
    const float* pts = (const float*)d_in[1];
    const float* Ws  = (const float*)d_in[2];
    const float* bs  = (const float*)d_in[3];
    const float* fW  = (const float*)d_in[4];
    float* out = (float*)d_out;

    const int n      = in_sizes[1] / 2;
    const int layers = in_sizes[2] / 4;
    const int nf4    = n / 2;

    const int grid = (nf4 + TPB - 1) / TPB;
    nignet_kernel<<<grid, TPB>>>(
        (const float4*)pts, Ws, bs, fW, (float4*)out, nf4, layers);
}

// round 7
// speedup vs baseline: 1.1352x; 1.0026x over previous
#include <cuda_runtime.h>
#include <cuda_fp16.h>

#define TPB 512
#define NBLOCKS 456          // 152 SMs * 3 resident blocks (persistent)
#define MAX_LAYERS 64
typedef unsigned long long ull;

// ---------- packed f32x2 primitives ----------
__device__ __forceinline__ ull f2fma(ull a, ull b, ull c) {
    ull d; asm("fma.rn.f32x2 %0, %1, %2, %3;" : "=l"(d) : "l"(a), "l"(b), "l"(c)); return d;
}
__device__ __forceinline__ ull f2mul(ull a, ull b) {
    ull d; asm("mul.rn.f32x2 %0, %1, %2;" : "=l"(d) : "l"(a), "l"(b)); return d;
}
__device__ __forceinline__ ull f2add(ull a, ull b) {
    ull d; asm("add.rn.f32x2 %0, %1, %2;" : "=l"(d) : "l"(a), "l"(b)); return d;
}
__device__ __forceinline__ ull pkf(float lo, float hi) {
    ull r; asm("mov.b64 %0, {%1, %2};" : "=l"(r) : "f"(lo), "f"(hi)); return r;
}
__device__ __forceinline__ ull pk2(float x) { return pkf(x, x); }
__device__ __forceinline__ void unpku(ull v, unsigned& lo, unsigned& hi) {
    asm("mov.b64 {%0, %1}, %2;" : "=r"(lo), "=r"(hi) : "l"(v));
}
__device__ __forceinline__ ull pku(unsigned lo, unsigned hi) {
    ull r; asm("mov.b64 %0, {%1, %2};" : "=l"(r) : "r"(lo), "r"(hi)); return r;
}
__device__ __forceinline__ void unpkf(ull v, float& lo, float& hi) {
    asm("mov.b64 {%0, %1}, %2;" : "=f"(lo), "=f"(hi) : "l"(v));
}

// MUFU-free odd tanh: tanh(x) = (u-1)/(u+1), u = e^{2x} = 2^(2x*log2e).
// No abs/sign transfer. 15 f32x2 (fma pipe) + ~10 int ops (alu). abs err ~1e-4.
__device__ __forceinline__ ull tanh2_fma(ull y) {
    ull w  = f2mul(y, pk2(2.885390081777927f));      // 2*log2e*x
    ull kf = f2add(w, pk2(12582912.0f));             // magic round; low bits = k
    ull kb = f2add(kf, pk2(-12582912.0f));           // k as float (exact)
    ull f  = f2fma(kb, pk2(-1.0f), w);               // f = w-k, |f|<=0.5
    ull p  = f2fma(f, pk2(0.0555042f), pk2(0.2422254f));
    p = f2fma(f, p, pk2(0.6931472f));
    p = f2fma(f, p, pk2(1.0f));                      // 2^f (>0 always)
    unsigned klo, khi, plo, phi;
    unpku(kf, klo, khi);
    unpku(p,  plo, phi);
    const int KMINi = 0x4B3FFF82;                    // k = -126
    const int KMAXi = 0x4B400040;                    // k = +64
    int kl = min(max((int)klo, KMINi), KMAXi);
    int kh = min(max((int)khi, KMINi), KMAXi);
    unsigned ulo = plo + ((unsigned)kl << 23);       // exponent insert (low 9 bits of kf)
    unsigned uhi = phi + ((unsigned)kh << 23);
    ull u = pku(ulo, uhi);                           // e^{2x}, in [2^-126, ~2e19]
    ull d = f2add(u, pk2(1.0f));                     // 1+u
    unsigned dlo, dhi;
    unpku(d, dlo, dhi);
    ull r  = pku(0x7EF311C3u - dlo, 0x7EF311C3u - dhi);  // ~1/d, rel err ~4%
    ull nd = d ^ 0x8000000080000000ull;              // -d (alu)
    r = f2mul(r, f2fma(nd, r, pk2(2.0f)));           // Newton 1
    r = f2mul(r, f2fma(nd, r, pk2(2.0f)));           // Newton 2 (err ~1e-5)
    ull num = f2add(u, pk2(-1.0f));                  // u-1
    return f2mul(num, r);                            // tanh(x)
}

__device__ __forceinline__ __half2 tanh_h2(__half2 x) {
    __half2 y;
    asm("tanh.approx.f16x2 %0, %1;"
        : "=r"(*reinterpret_cast<unsigned int*>(&y))
        : "r"(*reinterpret_cast<const unsigned int*>(&x)));
    return y;
}

// final matvec + L2 normalize (fp32)
__device__ __forceinline__ float2 fin_norm(float x0, float x1,
                                           float f00, float f01, float f10, float f11) {
    float o0 = fmaf(f00, x0, f01 * x1);
    float o1 = fmaf(f10, x0, f11 * x1);
    float s  = fmaf(o0, o0, o1 * o1);
    float inv = rsqrtf(s);
    inv = inv * fmaf(-0.5f * s * inv, inv, 1.5f);
    if (s < 1e-24f) inv = 1e12f;                     // eps=1e-12 clamp
    return make_float2(o0 * inv, o1 * inv);
}

// Persistent warp-specialized kernel. 16 warps/block: wid 0-3 = B (fma-pipe tanh),
// wid 4-15 = A (MUFU half2 tanh). SMSP=wid%4 -> every SMSP holds 3A+1B (x3 blocks).
// A-class grid-strides region [0,csplit), B-class [csplit,nf4)  (csplit ~ 25/32 of data,
// the MUFU-vs-fma balance point). 4 points (2 float4) per thread-iteration for ILP.
// z-form: z = 2x for l>=1 (0.5 folded into W); final normalize is scale-invariant.
__global__ __launch_bounds__(TPB, 3) void nignet_kernel(
    const float4* __restrict__ pts,
    const float*  __restrict__ Ws,    // (L,2,2)
    const float*  __restrict__ bs,    // (L,2)
    const float*  __restrict__ fW,    // (2,2)
    float4* __restrict__ out,
    int nf4, int csplit, int layers)
{
    __shared__ __align__(16) __half2 sw[MAX_LAYERS][4];
    __shared__ __align__(8)  __half2 sb[MAX_LAYERS][2];
    __shared__ __align__(16) ull     swB[MAX_LAYERS][6];
    __shared__ float sf[4];

    const int tid = threadIdx.x;
    if (tid < layers) {
        const float scl = (tid == 0) ? 1.0f : 0.5f;
        float4 w = ((const float4*)Ws)[tid];
        float2 b = ((const float2*)bs)[tid];
        float w00 = w.x * scl, w01 = w.y * scl, w10 = w.z * scl, w11 = w.w * scl;
        sw[tid][0] = __float2half2_rn(w00);
        sw[tid][1] = __float2half2_rn(w01);
        sw[tid][2] = __float2half2_rn(w10);
        sw[tid][3] = __float2half2_rn(w11);
        sb[tid][0] = __float2half2_rn(b.x);
        sb[tid][1] = __float2half2_rn(b.y);
        swB[tid][0] = pk2(w00);
        swB[tid][1] = pk2(w01);
        swB[tid][2] = pk2(w10);
        swB[tid][3] = pk2(w11);
        swB[tid][4] = pk2(b.x);
        swB[tid][5] = pk2(b.y);
    }
    if (tid < 4) sf[tid] = fW[tid];
    __syncthreads();

    const int wid  = tid >> 5;
    const int lane = tid & 31;
    const float f00 = sf[0], f01 = sf[1], f10 = sf[2], f11 = sf[3];
    const float4 zero4 = make_float4(0.f, 0.f, 0.f, 0.f);

    if (wid >= 4) {
        // ================= A class: MUFU half2 tanh, region [0, csplit) ==========
        const int g      = blockIdx.x * 12 + (wid - 4);
        const int stride = NBLOCKS * 12 * 64;            // 64 f4 per warp-iter
        for (int base = g * 64; base < csplit; base += stride) {
            const int i0 = base + lane, i1 = base + lane + 32;
            const bool v0 = i0 < csplit, v1 = i1 < csplit;
            float4 P = v0 ? pts[i0] : zero4;
            float4 Q = v1 ? pts[i1] : zero4;
            __half2 Xa0 = __floats2half2_rn(P.x, P.z);
            __half2 Xa1 = __floats2half2_rn(P.y, P.w);
            __half2 Xb0 = __floats2half2_rn(Q.x, Q.z);
            __half2 Xb1 = __floats2half2_rn(Q.y, Q.w);
            #pragma unroll 2
            for (int l = 0; l < layers; ++l) {
                const __half2 w00 = sw[l][0], w01 = sw[l][1];
                const __half2 w10 = sw[l][2], w11 = sw[l][3];
                const __half2 b0  = sb[l][0], b1  = sb[l][1];
                __half2 ya0 = __hfma2(w00, Xa0, __hfma2(w01, Xa1, b0));
                __half2 ya1 = __hfma2(w10, Xa0, __hfma2(w11, Xa1, b1));
                __half2 yb0 = __hfma2(w00, Xb0, __hfma2(w01, Xb1, b0));
                __half2 yb1 = __hfma2(w10, Xb0, __hfma2(w11, Xb1, b1));
                Xa0 = __hadd2(tanh_h2(ya0), ya0);
                Xa1 = __hadd2(tanh_h2(ya1), ya1);
                Xb0 = __hadd2(tanh_h2(yb0), yb0);
                Xb1 = __hadd2(tanh_h2(yb1), yb1);
            }
            float2 a0 = __half22float2(Xa0), a1 = __half22float2(Xa1);
            float2 b0 = __half22float2(Xb0), b1 = __half22float2(Xb1);
            float2 r0 = fin_norm(a0.x, a1.x, f00, f01, f10, f11);
            float2 r1 = fin_norm(a0.y, a1.y, f00, f01, f10, f11);
            float2 r2 = fin_norm(b0.x, b1.x, f00, f01, f10, f11);
            float2 r3 = fin_norm(b0.y, b1.y, f00, f01, f10, f11);
            if (v0) out[i0] = make_float4(r0.x, r0.y, r1.x, r1.y);
            if (v1) out[i1] = make_float4(r2.x, r2.y, r3.x, r3.y);
        }
    } else {
        // ================= B class: fma-pipe tanh, region [csplit, nf4) ==========
        const int g      = blockIdx.x * 4 + wid;
        const int stride = NBLOCKS * 4 * 64;
        for (int base = csplit + g * 64; base < nf4; base += stride) {
            const int i0 = base + lane, i1 = base + lane + 32;
            const bool v0 = i0 < nf4, v1 = i1 < nf4;
            float4 P = v0 ? pts[i0] : zero4;
            float4 Q = v1 ? pts[i1] : zero4;
            ull XP0 = pkf(P.x, P.z), XP1 = pkf(P.y, P.w);
            ull XQ0 = pkf(Q.x, Q.z), XQ1 = pkf(Q.y, Q.w);
            #pragma unroll 1
            for (int l = 0; l < layers; ++l) {
                const ull w00 = swB[l][0], w01 = swB[l][1];
                const ull w10 = swB[l][2], w11 = swB[l][3];
                const ull b0  = swB[l][4], b1  = swB[l][5];
                ull yp0 = f2fma(w00, XP0, f2fma(w01, XP1, b0));
                ull yp1 = f2fma(w10, XP0, f2fma(w11, XP1, b1));
                ull yq0 = f2fma(w00, XQ0, f2fma(w01, XQ1, b0));
                ull yq1 = f2fma(w10, XQ0, f2fma(w11, XQ1, b1));
                XP0 = f2add(tanh2_fma(yp0), yp0);
                XP1 = f2add(tanh2_fma(yp1), yp1);
                XQ0 = f2add(tanh2_fma(yq0), yq0);
                XQ1 = f2add(tanh2_fma(yq1), yq1);
            }
            float p0x, p1x, p0y, p1y, q0x, q1x, q0y, q1y;
            unpkf(XP0, p0x, p1x);
            unpkf(XP1, p0y, p1y);
            unpkf(XQ0, q0x, q1x);
            unpkf(XQ1, q0y, q1y);
            float2 r0 = fin_norm(p0x, p0y, f00, f01, f10, f11);
            float2 r1 = fin_norm(p1x, p1y, f00, f01, f10, f11);
            float2 r2 = fin_norm(q0x, q0y, f00, f01, f10, f11);
            float2 r3 = fin_norm(q1x, q1y, f00, f01, f10, f11);
            if (v0) out[i0] = make_float4(r0.x, r0.y, r1.x, r1.y);
            if (v1) out[i1] = make_float4(r2.x, r2.y, r3.x, r3.y);
        }
    }
}

extern "C" void kernel_launch(void* const* d_in, const int* in_sizes, int n_in,
                              void* d_out, int out_size) {
    // metadata order: T(1), closed_manifold(N*2), Ws(L*4), bs(L*2), final_W(4)
    const float* pts = (const float*)d_in[1];
    const float* Ws  = (const float*)d_in[2];
    const float* bs  = (const float*)d_in[3];
    const float* fW  = (const float*)d_in[4];
    float* out = (float*)d_out;

    const int n      = in_sizes[1] / 2;
    const int layers = in_sizes[2] / 4;
    const int nf4    = n / 2;

    // A-class (MUFU) handles ~25/32 of the data; B-class (fma) the rest.
    // 64-f4 aligned so warp chunks stay full.
    long long c = ((long long)nf4 * 25) / 32;
    int csplit = (int)(c & ~63LL);
    if (csplit > nf4) csplit = nf4;

    nignet_kernel<<<NBLOCKS, TPB>>>(
        (const float4*)pts, Ws, bs, fW, (float4*)out, nf4, csplit, layers);
}

// round 8
// speedup vs baseline: 1.1838x; 1.0428x over previous
#include <cuda_runtime.h>
#include <cuda_fp16.h>

#define TPB 256
#define NBLOCKS 608            // 152 SMs * 4 resident (persistent)
#define MAX_LAYERS 64
typedef unsigned long long ull;

// ---------- packed f32x2 primitives ----------
__device__ __forceinline__ ull f2fma(ull a, ull b, ull c) {
    ull d; asm("fma.rn.f32x2 %0, %1, %2, %3;" : "=l"(d) : "l"(a), "l"(b), "l"(c)); return d;
}
__device__ __forceinline__ ull f2mul(ull a, ull b) {
    ull d; asm("mul.rn.f32x2 %0, %1, %2;" : "=l"(d) : "l"(a), "l"(b)); return d;
}
__device__ __forceinline__ ull f2add(ull a, ull b) {
    ull d; asm("add.rn.f32x2 %0, %1, %2;" : "=l"(d) : "l"(a), "l"(b)); return d;
}
__device__ __forceinline__ ull pkf(float lo, float hi) {
    ull r; asm("mov.b64 %0, {%1, %2};" : "=l"(r) : "f"(lo), "f"(hi)); return r;
}
__device__ __forceinline__ ull pk2(float x) { return pkf(x, x); }
__device__ __forceinline__ void unpku(ull v, unsigned& lo, unsigned& hi) {
    asm("mov.b64 {%0, %1}, %2;" : "=r"(lo), "=r"(hi) : "l"(v));
}
__device__ __forceinline__ ull pku(unsigned lo, unsigned hi) {
    ull r; asm("mov.b64 %0, {%1, %2};" : "=l"(r) : "r"(lo), "r"(hi)); return r;
}
__device__ __forceinline__ void unpkf(ull v, float& lo, float& hi) {
    asm("mov.b64 {%0, %1}, %2;" : "=f"(lo), "=f"(hi) : "l"(v));
}

// MUFU-free odd tanh: tanh(x) = (u-1)/(u+1), u = e^{2x} = 2^(2x*log2e).
// 15 f32x2 (fma pipe) + ~10 int ops (alu). abs err ~1e-4.
__device__ __forceinline__ ull tanh2_fma(ull y) {
    ull w  = f2mul(y, pk2(2.885390081777927f));      // 2*log2e*x
    ull kf = f2add(w, pk2(12582912.0f));             // magic round; low bits = k
    ull kb = f2add(kf, pk2(-12582912.0f));           // k as float (exact)
    ull f  = f2fma(kb, pk2(-1.0f), w);               // f = w-k, |f|<=0.5
    ull p  = f2fma(f, pk2(0.0555042f), pk2(0.2422254f));
    p = f2fma(f, p, pk2(0.6931472f));
    p = f2fma(f, p, pk2(1.0f));                      // 2^f (>0)
    unsigned klo, khi, plo, phi;
    unpku(kf, klo, khi);
    unpku(p,  plo, phi);
    const int KMINi = 0x4B3FFF82;                    // k = -126
    const int KMAXi = 0x4B400040;                    // k = +64
    int kl = min(max((int)klo, KMINi), KMAXi);
    int kh = min(max((int)khi, KMINi), KMAXi);
    unsigned ulo = plo + ((unsigned)kl << 23);       // exponent insert
    unsigned uhi = phi + ((unsigned)kh << 23);
    ull u = pku(ulo, uhi);                           // e^{2x}
    ull d = f2add(u, pk2(1.0f));                     // 1+u
    unsigned dlo, dhi;
    unpku(d, dlo, dhi);
    ull r  = pku(0x7EF311C3u - dlo, 0x7EF311C3u - dhi);  // ~1/d seed
    ull nd = d ^ 0x8000000080000000ull;              // -d
    r = f2mul(r, f2fma(nd, r, pk2(2.0f)));           // Newton 1
    r = f2mul(r, f2fma(nd, r, pk2(2.0f)));           // Newton 2
    ull num = f2add(u, pk2(-1.0f));                  // u-1
    return f2mul(num, r);                            // tanh(x)
}

__device__ __forceinline__ __half2 tanh_h2(__half2 x) {
    __half2 y;
    asm("tanh.approx.f16x2 %0, %1;"
        : "=r"(*reinterpret_cast<unsigned int*>(&y))
        : "r"(*reinterpret_cast<const unsigned int*>(&x)));
    return y;
}

__device__ __forceinline__ float2 fin_norm(float x0, float x1,
                                           float f00, float f01, float f10, float f11) {
    float o0 = fmaf(f00, x0, f01 * x1);
    float o1 = fmaf(f10, x0, f11 * x1);
    float s  = fmaf(o0, o0, o1 * o1);
    float inv = rsqrtf(s);
    inv = inv * fmaf(-0.5f * s * inv, inv, 1.5f);
    if (s < 1e-24f) inv = 1e12f;                     // eps=1e-12 clamp
    return make_float2(o0 * inv, o1 * inv);
}

// Homogeneous hybrid: EVERY thread carries 8 MUFU-path points (4 half2 pairs)
// + 2 fma-path points (1 f32x2 pair) per iteration. Each warp feeds both the
// MUFU pipe (128 cyc/layer) and the fma pipe (120 cyc/layer) -> self-balanced;
// occupancy/churn/tails can't strand a pipe. 0.4 cyc/pt-layer vs 0.5 pure-MUFU.
// Persistent grid-stride over 160-float4 chunks (5 f4/thread: 4 A + 1 B).
// z-form: z = 2x for l>=1 (0.5 folded into W); final normalize is scale-invariant.
__global__ __launch_bounds__(TPB, 4) void nignet_kernel(
    const float4* __restrict__ pts,
    const float*  __restrict__ Ws,    // (L,2,2)
    const float*  __restrict__ bs,    // (L,2)
    const float*  __restrict__ fW,    // (2,2)
    float4* __restrict__ out,
    int nf4, int layers)
{
    __shared__ __align__(16) __half2 sw[MAX_LAYERS][4];
    __shared__ __align__(8)  __half2 sb[MAX_LAYERS][2];
    __shared__ __align__(16) ull     swB[MAX_LAYERS][6];
    __shared__ float sf[4];

    const int tid = threadIdx.x;
    if (tid < layers) {
        const float scl = (tid == 0) ? 1.0f : 0.5f;
        float4 w = ((const float4*)Ws)[tid];
        float2 b = ((const float2*)bs)[tid];
        float w00 = w.x * scl, w01 = w.y * scl, w10 = w.z * scl, w11 = w.w * scl;
        sw[tid][0] = __float2half2_rn(w00);
        sw[tid][1] = __float2half2_rn(w01);
        sw[tid][2] = __float2half2_rn(w10);
        sw[tid][3] = __float2half2_rn(w11);
        sb[tid][0] = __float2half2_rn(b.x);
        sb[tid][1] = __float2half2_rn(b.y);
        swB[tid][0] = pk2(w00);
        swB[tid][1] = pk2(w01);
        swB[tid][2] = pk2(w10);
        swB[tid][3] = pk2(w11);
        swB[tid][4] = pk2(b.x);
        swB[tid][5] = pk2(b.y);
    }
    if (tid < 4) sf[tid] = fW[tid];
    __syncthreads();

    const int wid  = tid >> 5;
    const int lane = tid & 31;
    const int gw   = blockIdx.x * (TPB / 32) + wid;      // global warp id
    const int G    = NBLOCKS * (TPB / 32);               // total warps
    const float f00 = sf[0], f01 = sf[1], f10 = sf[2], f11 = sf[3];
    const float4 zero4 = make_float4(0.f, 0.f, 0.f, 0.f);

    for (int base = gw * 160; base < nf4; base += G * 160) {
        // ---- load 4 A-chunks + 1 B-chunk (coalesced, lane-strided) ----
        int i0 = base + lane,       i1 = base + 32 + lane;
        int i2 = base + 64 + lane,  i3 = base + 96 + lane;
        int i4 = base + 128 + lane;
        bool v0 = i0 < nf4, v1 = i1 < nf4, v2 = i2 < nf4, v3 = i3 < nf4, v4 = i4 < nf4;
        float4 P0 = v0 ? pts[i0] : zero4;
        float4 P1 = v1 ? pts[i1] : zero4;
        float4 P2 = v2 ? pts[i2] : zero4;
        float4 P3 = v3 ? pts[i3] : zero4;
        float4 PB = v4 ? pts[i4] : zero4;

        __half2 Xa0 = __floats2half2_rn(P0.x, P0.z), Xa1 = __floats2half2_rn(P0.y, P0.w);
        __half2 Xb0 = __floats2half2_rn(P1.x, P1.z), Xb1 = __floats2half2_rn(P1.y, P1.w);
        __half2 Xc0 = __floats2half2_rn(P2.x, P2.z), Xc1 = __floats2half2_rn(P2.y, P2.w);
        __half2 Xd0 = __floats2half2_rn(P3.x, P3.z), Xd1 = __floats2half2_rn(P3.y, P3.w);
        ull     XB0 = pkf(PB.x, PB.z),               XB1 = pkf(PB.y, PB.w);

        #pragma unroll 1
        for (int l = 0; l < layers; ++l) {
            const __half2 w00 = sw[l][0], w01 = sw[l][1];
            const __half2 w10 = sw[l][2], w11 = sw[l][3];
            const __half2 hb0 = sb[l][0], hb1 = sb[l][1];
            const ull W00 = swB[l][0], W01 = swB[l][1];
            const ull W10 = swB[l][2], W11 = swB[l][3];
            const ull B0  = swB[l][4], B1  = swB[l][5];

            // B pair first (long fma chain starts early, overlaps A's MUFU waits)
            ull yB0 = f2fma(W00, XB0, f2fma(W01, XB1, B0));
            ull yB1 = f2fma(W10, XB0, f2fma(W11, XB1, B1));

            __half2 ya0 = __hfma2(w00, Xa0, __hfma2(w01, Xa1, hb0));
            __half2 ya1 = __hfma2(w10, Xa0, __hfma2(w11, Xa1, hb1));
            __half2 yb0 = __hfma2(w00, Xb0, __hfma2(w01, Xb1, hb0));
            __half2 yb1 = __hfma2(w10, Xb0, __hfma2(w11, Xb1, hb1));
            __half2 yc0 = __hfma2(w00, Xc0, __hfma2(w01, Xc1, hb0));
            __half2 yc1 = __hfma2(w10, Xc0, __hfma2(w11, Xc1, hb1));
            __half2 yd0 = __hfma2(w00, Xd0, __hfma2(w01, Xd1, hb0));
            __half2 yd1 = __hfma2(w10, Xd0, __hfma2(w11, Xd1, hb1));

            XB0 = f2add(tanh2_fma(yB0), yB0);
            XB1 = f2add(tanh2_fma(yB1), yB1);

            Xa0 = __hadd2(tanh_h2(ya0), ya0);
            Xa1 = __hadd2(tanh_h2(ya1), ya1);
            Xb0 = __hadd2(tanh_h2(yb0), yb0);
            Xb1 = __hadd2(tanh_h2(yb1), yb1);
            Xc0 = __hadd2(tanh_h2(yc0), yc0);
            Xc1 = __hadd2(tanh_h2(yc1), yc1);
            Xd0 = __hadd2(tanh_h2(yd0), yd0);
            Xd1 = __hadd2(tanh_h2(yd1), yd1);
        }

        // ---- epilogue + stores ----
        {
            float2 a0 = __half22float2(Xa0), a1 = __half22float2(Xa1);
            float2 r0 = fin_norm(a0.x, a1.x, f00, f01, f10, f11);
            float2 r1 = fin_norm(a0.y, a1.y, f00, f01, f10, f11);
            if (v0) out[i0] = make_float4(r0.x, r0.y, r1.x, r1.y);
        }
        {
            float2 a0 = __half22float2(Xb0), a1 = __half22float2(Xb1);
            float2 r0 = fin_norm(a0.x, a1.x, f00, f01, f10, f11);
            float2 r1 = fin_norm(a0.y, a1.y, f00, f01, f10, f11);
            if (v1) out[i1] = make_float4(r0.x, r0.y, r1.x, r1.y);
        }
        {
            float2 a0 = __half22float2(Xc0), a1 = __half22float2(Xc1);
            float2 r0 = fin_norm(a0.x, a1.x, f00, f01, f10, f11);
            float2 r1 = fin_norm(a0.y, a1.y, f00, f01, f10, f11);
            if (v2) out[i2] = make_float4(r0.x, r0.y, r1.x, r1.y);
        }
        {
            float2 a0 = __half22float2(Xd0), a1 = __half22float2(Xd1);
            float2 r0 = fin_norm(a0.x, a1.x, f00, f01, f10, f11);
            float2 r1 = fin_norm(a0.y, a1.y, f00, f01, f10, f11);
            if (v3) out[i3] = make_float4(r0.x, r0.y, r1.x, r1.y);
        }
        {
            float b0x, b1x, b0y, b1y;
            unpkf(XB0, b0x, b1x);
            unpkf(XB1, b0y, b1y);
            float2 r0 = fin_norm(b0x, b0y, f00, f01, f10, f11);
            float2 r1 = fin_norm(b1x, b1y, f00, f01, f10, f11);
            if (v4) out[i4] = make_float4(r0.x, r0.y, r1.x, r1.y);
        }
    }
}

extern "C" void kernel_launch(void* const* d_in, const int* in_sizes, int n_in,
                              void* d_out, int out_size) {
    // metadata order: T(1), closed_manifold(N*2), Ws(L*4), bs(L*2), final_W(4)
    const float* pts = (const float*)d_in[1];
    const float* Ws  = (const float*)d_in[2];
    const float* bs  = (const float*)d_in[3];
    const float* fW  = (const float*)d_in[4];
    float* out = (float*)d_out;

    const int n      = in_sizes[1] / 2;
    const int layers = in_sizes[2] / 4;
    const int nf4    = n / 2;

    nignet_kernel<<<NBLOCKS, TPB>>>(
        (const float4*)pts, Ws, bs, fW, (float4*)out, nf4, layers);
}

// round 9
// speedup vs baseline: 1.2062x; 1.0189x over previous
#include <cuda_runtime.h>
#include <cuda_fp16.h>

#define TPB 256
#define NBLOCKS 608            // persistent; residency-agnostic (work stealing)
#define MAX_LAYERS 64
#define CHUNK 160              // float4 per warp-chunk: 4 A-f4 + 1 B-f4 per lane
typedef unsigned long long ull;

__device__ unsigned g_chunk_ctr;

__global__ void reset_ctr_kernel() { g_chunk_ctr = 0u; }

// ---------- packed f32x2 primitives ----------
__device__ __forceinline__ ull f2fma(ull a, ull b, ull c) {
    ull d; asm("fma.rn.f32x2 %0, %1, %2, %3;" : "=l"(d) : "l"(a), "l"(b), "l"(c)); return d;
}
__device__ __forceinline__ ull f2mul(ull a, ull b) {
    ull d; asm("mul.rn.f32x2 %0, %1, %2;" : "=l"(d) : "l"(a), "l"(b)); return d;
}
__device__ __forceinline__ ull f2add(ull a, ull b) {
    ull d; asm("add.rn.f32x2 %0, %1, %2;" : "=l"(d) : "l"(a), "l"(b)); return d;
}
__device__ __forceinline__ ull pkf(float lo, float hi) {
    ull r; asm("mov.b64 %0, {%1, %2};" : "=l"(r) : "f"(lo), "f"(hi)); return r;
}
__device__ __forceinline__ ull pk2(float x) { return pkf(x, x); }
__device__ __forceinline__ void unpku(ull v, unsigned& lo, unsigned& hi) {
    asm("mov.b64 {%0, %1}, %2;" : "=r"(lo), "=r"(hi) : "l"(v));
}
__device__ __forceinline__ ull pku(unsigned lo, unsigned hi) {
    ull r; asm("mov.b64 %0, {%1, %2};" : "=l"(r) : "r"(lo), "r"(hi)); return r;
}
__device__ __forceinline__ void unpkf(ull v, float& lo, float& hi) {
    asm("mov.b64 {%0, %1}, %2;" : "=f"(lo), "=f"(hi) : "l"(v));
}

// MUFU-free packed tanh: Eigen-style 13/6 rational, coefficients normalized
// so leading num/den constants are 1.0. 16 f32x2 (fma pipe) + 4 alu
// (2 FMNMX clamp + 2 magic-sub). abs err ~1e-6 on the clamped range.
__device__ __forceinline__ ull tanh2_fma(ull y) {
    const float C = 7.90531110763549805f;
    float ylo, yhi;
    unpkf(y, ylo, yhi);                              // register rename (free)
    ylo = fminf(fmaxf(ylo, -C), C);                  // FMNMX (alu)
    yhi = fminf(fmaxf(yhi, -C), C);
    ull x  = pkf(ylo, yhi);
    ull x2 = f2mul(x, x);
    // num/x = 1 + c3 x^2 + ... + c13 x^12  (normalized by a1)
    ull p = f2fma(x2, pk2(-5.641877e-14f), pk2(4.087423e-11f));
    p = f2fma(x2, p, pk2(-1.758383e-08f));
    p = f2fma(x2, p, pk2(1.046751e-05f));
    p = f2fma(x2, p, pk2(3.036104e-03f));
    p = f2fma(x2, p, pk2(0.13022513f));
    p = f2fma(x2, p, pk2(1.0f));
    p = f2mul(p, x);                                 // numerator
    // den = 1 + d2 x^2 + d4 x^4 + d6 x^6 (normalized by b0), always >= 1
    ull q = f2fma(x2, pk2(2.448660e-04f), pk2(2.422274e-02f));
    q = f2fma(x2, q, pk2(0.46355807f));
    q = f2fma(x2, q, pk2(1.0f));
    // 1/q: magic seed + 2 Newton (q in [1, ~184])
    unsigned qlo, qhi;
    unpku(q, qlo, qhi);
    ull r  = pku(0x7EF311C3u - qlo, 0x7EF311C3u - qhi);
    ull nq = q ^ 0x8000000080000000ull;              // -q
    r = f2mul(r, f2fma(nq, r, pk2(2.0f)));
    r = f2mul(r, f2fma(nq, r, pk2(2.0f)));
    return f2mul(p, r);                              // tanh(x)
}

__device__ __forceinline__ __half2 tanh_h2(__half2 x) {
    __half2 y;
    asm("tanh.approx.f16x2 %0, %1;"
        : "=r"(*reinterpret_cast<unsigned int*>(&y))
        : "r"(*reinterpret_cast<const unsigned int*>(&x)));
    return y;
}

__device__ __forceinline__ float2 fin_norm(float x0, float x1,
                                           float f00, float f01, float f10, float f11) {
    float o0 = fmaf(f00, x0, f01 * x1);
    float o1 = fmaf(f10, x0, f11 * x1);
    float s  = fmaf(o0, o0, o1 * o1);
    float inv = rsqrtf(s);
    inv = inv * fmaf(-0.5f * s * inv, inv, 1.5f);
    if (s < 1e-24f) inv = 1e12f;                     // eps=1e-12 clamp
    return make_float2(o0 * inv, o1 * inv);
}

// Homogeneous hybrid + dynamic work stealing. Every thread: 8 MUFU-path points
// (4 half2 pairs) + 2 fma-path points (1 f32x2 pair) per chunk -> each warp
// self-balances MUFU (128 cyc/layer) vs fma (~108 cyc/layer). Warps pull
// 160-f4 chunks from a global atomic counter: no iteration quantization, no
// residency sensitivity, tail = fraction of one chunk.
// z-form: z = 2x for l>=1 (0.5 folded into W); final normalize is scale-invariant.
__global__ __launch_bounds__(TPB, 3) void nignet_kernel(
    const float4* __restrict__ pts,
    const float*  __restrict__ Ws,    // (L,2,2)
    const float*  __restrict__ bs,    // (L,2)
    const float*  __restrict__ fW,    // (2,2)
    float4* __restrict__ out,
    int nf4, int nchunks, int layers)
{
    __shared__ __align__(16) __half2 sw[MAX_LAYERS][4];
    __shared__ __align__(8)  __half2 sb[MAX_LAYERS][2];
    __shared__ __align__(16) ull     swB[MAX_LAYERS][6];
    __shared__ float sf[4];

    const int tid = threadIdx.x;
    if (tid < layers) {
        const float scl = (tid == 0) ? 1.0f : 0.5f;
        float4 w = ((const float4*)Ws)[tid];
        float2 b = ((const float2*)bs)[tid];
        float w00 = w.x * scl, w01 = w.y * scl, w10 = w.z * scl, w11 = w.w * scl;
        sw[tid][0] = __float2half2_rn(w00);
        sw[tid][1] = __float2half2_rn(w01);
        sw[tid][2] = __float2half2_rn(w10);
        sw[tid][3] = __float2half2_rn(w11);
        sb[tid][0] = __float2half2_rn(b.x);
        sb[tid][1] = __float2half2_rn(b.y);
        swB[tid][0] = pk2(w00);
        swB[tid][1] = pk2(w01);
        swB[tid][2] = pk2(w10);
        swB[tid][3] = pk2(w11);
        swB[tid][4] = pk2(b.x);
        swB[tid][5] = pk2(b.y);
    }
    if (tid < 4) sf[tid] = fW[tid];
    __syncthreads();

    const int lane = tid & 31;
    const float f00 = sf[0], f01 = sf[1], f10 = sf[2], f11 = sf[3];
    const float4 zero4 = make_float4(0.f, 0.f, 0.f, 0.f);

    for (;;) {
        unsigned c = 0;
        if (lane == 0) c = atomicAdd(&g_chunk_ctr, 1u);
        c = __shfl_sync(0xFFFFFFFFu, c, 0);
        if (c >= (unsigned)nchunks) break;
        const int base = (int)c * CHUNK;

        const int i0 = base + lane,       i1 = base + 32 + lane;
        const int i2 = base + 64 + lane,  i3 = base + 96 + lane;
        const int i4 = base + 128 + lane;
        const bool v0 = i0 < nf4, v1 = i1 < nf4, v2 = i2 < nf4,
                   v3 = i3 < nf4, v4 = i4 < nf4;
        float4 P0 = v0 ? pts[i0] : zero4;
        float4 P1 = v1 ? pts[i1] : zero4;
        float4 P2 = v2 ? pts[i2] : zero4;
        float4 P3 = v3 ? pts[i3] : zero4;
        float4 PB = v4 ? pts[i4] : zero4;

        __half2 Xa0 = __floats2half2_rn(P0.x, P0.z), Xa1 = __floats2half2_rn(P0.y, P0.w);
        __half2 Xb0 = __floats2half2_rn(P1.x, P1.z), Xb1 = __floats2half2_rn(P1.y, P1.w);
        __half2 Xc0 = __floats2half2_rn(P2.x, P2.z), Xc1 = __floats2half2_rn(P2.y, P2.w);
        __half2 Xd0 = __floats2half2_rn(P3.x, P3.z), Xd1 = __floats2half2_rn(P3.y, P3.w);
        ull     XB0 = pkf(PB.x, PB.z),               XB1 = pkf(PB.y, PB.w);

        #pragma unroll 1
        for (int l = 0; l < layers; ++l) {
            const __half2 w00 = sw[l][0], w01 = sw[l][1];
            const __half2 w10 = sw[l][2], w11 = sw[l][3];
            const __half2 hb0 = sb[l][0], hb1 = sb[l][1];
            const ull W00 = swB[l][0], W01 = swB[l][1];
            const ull W10 = swB[l][2], W11 = swB[l][3];
            const ull B0  = swB[l][4], B1  = swB[l][5];

            // B pair first: its long fma chain overlaps the A MUFU waits
            ull yB0 = f2fma(W00, XB0, f2fma(W01, XB1, B0));
            ull yB1 = f2fma(W10, XB0, f2fma(W11, XB1, B1));

            __half2 ya0 = __hfma2(w00, Xa0, __hfma2(w01, Xa1, hb0));
            __half2 ya1 = __hfma2(w10, Xa0, __hfma2(w11, Xa1, hb1));
            __half2 yb0 = __hfma2(w00, Xb0, __hfma2(w01, Xb1, hb0));
            __half2 yb1 = __hfma2(w10, Xb0, __hfma2(w11, Xb1, hb1));
            __half2 yc0 = __hfma2(w00, Xc0, __hfma2(w01, Xc1, hb0));
            __half2 yc1 = __hfma2(w10, Xc0, __hfma2(w11, Xc1, hb1));
            __half2 yd0 = __hfma2(w00, Xd0, __hfma2(w01, Xd1, hb0));
            __half2 yd1 = __hfma2(w10, Xd0, __hfma2(w11, Xd1, hb1));

            XB0 = f2add(tanh2_fma(yB0), yB0);
            XB1 = f2add(tanh2_fma(yB1), yB1);

            Xa0 = __hadd2(tanh_h2(ya0), ya0);
            Xa1 = __hadd2(tanh_h2(ya1), ya1);
            Xb0 = __hadd2(tanh_h2(yb0), yb0);
            Xb1 = __hadd2(tanh_h2(yb1), yb1);
            Xc0 = __hadd2(tanh_h2(yc0), yc0);
            Xc1 = __hadd2(tanh_h2(yc1), yc1);
            Xd0 = __hadd2(tanh_h2(yd0), yd0);
            Xd1 = __hadd2(tanh_h2(yd1), yd1);
        }

        {
            float2 a0 = __half22float2(Xa0), a1 = __half22float2(Xa1);
            float2 r0 = fin_norm(a0.x, a1.x, f00, f01, f10, f11);
            float2 r1 = fin_norm(a0.y, a1.y, f00, f01, f10, f11);
            if (v0) out[i0] = make_float4(r0.x, r0.y, r1.x, r1.y);
        }
        {
            float2 a0 = __half22float2(Xb0), a1 = __half22float2(Xb1);
            float2 r0 = fin_norm(a0.x, a1.x, f00, f01, f10, f11);
            float2 r1 = fin_norm(a0.y, a1.y, f00, f01, f10, f11);
            if (v1) out[i1] = make_float4(r0.x, r0.y, r1.x, r1.y);
        }
        {
            float2 a0 = __half22float2(Xc0), a1 = __half22float2(Xc1);
            float2 r0 = fin_norm(a0.x, a1.x, f00, f01, f10, f11);
            float2 r1 = fin_norm(a0.y, a1.y, f00, f01, f10, f11);
            if (v2) out[i2] = make_float4(r0.x, r0.y, r1.x, r1.y);
        }
        {
            float2 a0 = __half22float2(Xd0), a1 = __half22float2(Xd1);
            float2 r0 = fin_norm(a0.x, a1.x, f00, f01, f10, f11);
            float2 r1 = fin_norm(a0.y, a1.y, f00, f01, f10, f11);
            if (v3) out[i3] = make_float4(r0.x, r0.y, r1.x, r1.y);
        }
        {
            float b0x, b1x, b0y, b1y;
            unpkf(XB0, b0x, b1x);
            unpkf(XB1, b0y, b1y);
            float2 r0 = fin_norm(b0x, b0y, f00, f01, f10, f11);
            float2 r1 = fin_norm(b1x, b1y, f00, f01, f10, f11);
            if (v4) out[i4] = make_float4(r0.x, r0.y, r1.x, r1.y);
        }
    }
}

extern "C" void kernel_launch(void* const* d_in, const int* in_sizes, int n_in,
                              void* d_out, int out_size) {
    // metadata order: T(1), closed_manifold(N*2), Ws(L*4), bs(L*2), final_W(4)
    const float* pts = (const float*)d_in[1];
    const float* Ws  = (const float*)d_in[2];
    const float* bs  = (const float*)d_in[3];
    const float* fW  = (const float*)d_in[4];
    float* out = (float*)d_out;

    const int n       = in_sizes[1] / 2;
    const int layers  = in_sizes[2] / 4;
    const int nf4     = n / 2;
    const int nchunks = (nf4 + CHUNK - 1) / CHUNK;

    reset_ctr_kernel<<<1, 1>>>();
    nignet_kernel<<<NBLOCKS, TPB>>>(
        (const float4*)pts, Ws, bs, fW, (float4*)out, nf4, nchunks, layers);
}